// round 15
// baseline (speedup 1.0000x reference)
#include <cuda_runtime.h>
#include <cstdint>

// Problem constants
#define LDIM   128
#define RDIM   2048
#define EDIM   32
#define FDIM   64
#define KTOT   2048
#define BATCH  8

// Tiling (R7 = 186us baseline): CTA = 128L x 128R x (ECH*64)k,
// 512 threads, thread tile 8L x 4R, dist in registers.
#define KT       16
#define RT       128
#define ECH      4
#define NSTAGE   ((ECH*FDIM)/KT)     // 16
#define NTHREADS 512
#define LDSROW   132                 // padded row: 2-way max STS conflict

// rbf(d,e) = exp(-((d-mu_e)/sigma)^2) = 2^(-(KC*(d-mu_e))^2)
#define KC_CONST   3.2029930899845557f
#define MU_STEP    (12.0f/31.0f)

__device__ __forceinline__ unsigned long long dup2(float x) {
    unsigned long long r;
    unsigned int u = __float_as_uint(x);
    asm("mov.b64 %0, {%1, %1};" : "=l"(r) : "r"(u));
    return r;
}
__device__ __forceinline__ void fma2(unsigned long long &acc,
                                     unsigned long long a,
                                     unsigned long long b) {
    asm("fma.rn.f32x2 %0, %1, %2, %0;" : "+l"(acc) : "l"(a), "l"(b));
}
__device__ __forceinline__ void unpack2(unsigned long long v, float &lo, float &hi) {
    unsigned int a, b;
    asm("mov.b64 {%0, %1}, %2;" : "=r"(a), "=r"(b) : "l"(v));
    lo = __uint_as_float(a);
    hi = __uint_as_float(b);
}
__device__ __forceinline__ float ex2a(float x) {
    float r; asm("ex2.approx.ftz.f32 %0, %1;" : "=f"(r) : "f"(x)); return r;
}
__device__ __forceinline__ float sqrta(float x) {
    float r; asm("sqrt.approx.f32 %0, %1;" : "=f"(r) : "f"(x)); return r;
}
__device__ __forceinline__ void cpasync4(uint32_t dst_smem, const float* src) {
    asm volatile("cp.async.ca.shared.global [%0], [%1], 4;"
                 :: "r"(dst_smem), "l"(src));
}
#define CP_COMMIT() asm volatile("cp.async.commit_group;" ::: "memory")
#define CP_WAIT0()  asm volatile("cp.async.wait_group 0;" ::: "memory")

__global__ void ff_init_kernel(float* out) {
    if (threadIdx.x < BATCH) out[threadIdx.x] = 0.0f;
}

__global__ void __launch_bounds__(NTHREADS, 1)
ff_main_kernel(const float* __restrict__ ligf,
               const float* __restrict__ recf,
               const float* __restrict__ ligc,
               const float* __restrict__ recc,
               float* __restrict__ out)
{
    // A tile [2][KT][LDSROW] + B tile [2][KT][LDSROW]  (33792 B)
    __shared__ __align__(16) float smem[2 * KT * LDSROW * 2];
    float* As = smem;
    float* Bs = smem + 2 * KT * LDSROW;

    const int tid  = threadIdx.x;
    const int lane = tid & 31;          // owns r = 4*lane .. 4*lane+3
    const int w    = tid >> 5;          // 0..15; owns l = w*8 .. w*8+7
    const int l0   = w * 8;

    const int rt = blockIdx.x;          // 0..15
    const int ec = blockIdx.y;          // 0..7
    const int b  = blockIdx.z;          // 0..7

    const int r0    = rt * RT;
    const int e0    = ec * ECH;
    const int kbase = e0 * FDIM;

    const float* Ag = ligf + (size_t)b * LDIM * KTOT + kbase;
    const float* Bg = recf + ((size_t)b * RDIM + r0) * KTOT + kbase;

    // staging: each thread copies 4 consecutive k for one row, per tile
    const int srow = tid >> 2;          // 0..127
    const int scol = (tid & 3) * 4;     // 0,4,8,12

    // smem byte addresses for this thread's 4 staged words (per tile, buf 0)
    const uint32_t As_u32 =
        (uint32_t)__cvta_generic_to_shared(As) + ((scol * LDSROW + srow) << 2);
    const uint32_t Bs_u32 =
        (uint32_t)__cvta_generic_to_shared(Bs) + ((scol * LDSROW + srow) << 2);
    const uint32_t BUFOFF = (uint32_t)(KT * LDSROW) << 2;   // bytes per buffer

    // ---- distances for this thread's 8x4 pairs (registers, R7 exact) ----
    float dist[8][4];
    {
        float lx[8], ly[8], lz[8];
        #pragma unroll
        for (int i = 0; i < 8; i++) {
            const float* p = ligc + ((size_t)b * LDIM + l0 + i) * 3;
            lx[i] = p[0]; ly[i] = p[1]; lz[i] = p[2];
        }
        #pragma unroll
        for (int j = 0; j < 4; j++) {
            const float* p = recc + ((size_t)b * RDIM + r0 + 4 * lane + j) * 3;
            float rx = p[0], ry = p[1], rz = p[2];
            #pragma unroll
            for (int i = 0; i < 8; i++) {
                float dx = lx[i] - rx, dy = ly[i] - ry, dz = lz[i] - rz;
                float dd = fmaf(dx, dx, fmaf(dy, dy, dz * dz));
                dist[i][j] = sqrta(dd);
            }
        }
    }

    // acc[p][j] = packed {l = l0+2p, l0+2p+1} x r = 4*lane+j
    unsigned long long acc[4][4];
    #pragma unroll
    for (int p = 0; p < 4; p++)
        #pragma unroll
        for (int j = 0; j < 4; j++)
            acc[p][j] = 0ULL;

    float u_acc = 0.0f;

    // ---- async-stage 0 into buffer 0 ----
    {
        const float* asrc = Ag + (size_t)srow * KTOT + scol;
        const float* bsrc = Bg + (size_t)srow * KTOT + scol;
        #pragma unroll
        for (int j = 0; j < 4; j++) {
            cpasync4(As_u32 + (uint32_t)(j * LDSROW) * 4, asrc + j);
            cpasync4(Bs_u32 + (uint32_t)(j * LDSROW) * 4, bsrc + j);
        }
        CP_COMMIT();
    }

    #pragma unroll 1
    for (int s = 0; s < NSTAGE; s++) {
        const int buf = s & 1;
        float* Asb = As + buf * (KT * LDSROW);
        float* Bsb = Bs + buf * (KT * LDSROW);

        CP_WAIT0();
        __syncthreads();

        // kick async copies for stage s+1 into the other buffer
        if (s + 1 < NSTAGE) {
            const uint32_t nbo = (uint32_t)((s + 1) & 1) * BUFOFF;
            const int ko = (s + 1) * KT + scol;
            const float* asrc = Ag + (size_t)srow * KTOT + ko;
            const float* bsrc = Bg + (size_t)srow * KTOT + ko;
            #pragma unroll
            for (int j = 0; j < 4; j++) {
                cpasync4(As_u32 + nbo + (uint32_t)(j * LDSROW) * 4, asrc + j);
                cpasync4(Bs_u32 + nbo + (uint32_t)(j * LDSROW) * 4, bsrc + j);
            }
            CP_COMMIT();
        }

        // ---- main compute: KT k-steps, 8L x 4R per thread ----
        #pragma unroll
        for (int k = 0; k < KT; k++) {
            // B first (feeds the longest chain: LDS -> dup2 -> FFMA2)
            float4 bf = *(const float4*)(Bsb + k * LDSROW + 4 * lane);
            unsigned long long a2[4];
            {
                const ulonglong2* Ar =
                    (const ulonglong2*)(Asb + k * LDSROW + l0);
                ulonglong2 t0 = Ar[0];
                ulonglong2 t1 = Ar[1];
                a2[0] = t0.x; a2[1] = t0.y; a2[2] = t1.x; a2[3] = t1.y;
            }
            unsigned long long b2[4];
            b2[0] = dup2(bf.x);
            b2[1] = dup2(bf.y);
            b2[2] = dup2(bf.z);
            b2[3] = dup2(bf.w);

            #pragma unroll
            for (int p = 0; p < 4; p++)
                #pragma unroll
                for (int j = 0; j < 4; j++)
                    fma2(acc[p][j], a2[p], b2[j]);
        }

        // ---- epilogue fold at each e boundary (every 4 stages) ----
        if ((s & 3) == 3) {
            const int e = e0 + (s >> 2);
            const float c2 = KC_CONST * MU_STEP * (float)e;
            #pragma unroll
            for (int p = 0; p < 4; p++) {
                #pragma unroll
                for (int j = 0; j < 4; j++) {
                    float dot0, dot1;
                    unpack2(acc[p][j], dot0, dot1);
                    float z0 = fmaf(dist[2 * p][j],     KC_CONST, -c2);
                    float z1 = fmaf(dist[2 * p + 1][j], KC_CONST, -c2);
                    u_acc = fmaf(ex2a(-z0 * z0), dot0, u_acc);
                    u_acc = fmaf(ex2a(-z1 * z1), dot1, u_acc);
                    acc[p][j] = 0ULL;
                }
            }
        }
    }

    // ---- block reduction + atomic accumulate into U[b] ----
    #pragma unroll
    for (int o = 16; o > 0; o >>= 1)
        u_acc += __shfl_xor_sync(0xffffffffu, u_acc, o);

    __syncthreads();                       // tiles done; reuse as scratch
    float* red = smem;
    if (lane == 0) red[w] = u_acc;
    __syncthreads();
    if (tid == 0) {
        float ssum = 0.0f;
        #pragma unroll
        for (int ww = 0; ww < NTHREADS / 32; ww++) ssum += red[ww];
        atomicAdd(out + b, ssum * 0.01f);  // ENERGY_SCALE
    }
}

extern "C" void kernel_launch(void* const* d_in, const int* in_sizes, int n_in,
                              void* d_out, int out_size) {
    (void)in_sizes; (void)n_in; (void)out_size;
    const float* lig_feat  = (const float*)d_in[0];
    const float* rec_feat  = (const float*)d_in[1];
    const float* lig_coord = (const float*)d_in[2];
    const float* rec_coord = (const float*)d_in[3];
    float* out = (float*)d_out;

    ff_init_kernel<<<1, 32>>>(out);

    // (16, 8, 8) = 1024 CTAs, 1 per SM
    dim3 grid(RDIM / RT, EDIM / ECH, BATCH);
    ff_main_kernel<<<grid, NTHREADS>>>(lig_feat, rec_feat,
                                       lig_coord, rec_coord, out);
}

// round 16
// speedup vs baseline: 1.4211x; 1.4211x over previous
#include <cuda_runtime.h>

// Problem constants
#define LDIM   128
#define RDIM   2048
#define EDIM   32
#define FDIM   64
#define KTOT   2048      // EDIM*FDIM, contiguous k per row
#define BATCH  8

// Tiling (R7 baseline): CTA = 128L x 128R x (ECH*64)k, 512 threads,
// thread tile 8L x 4R, dist in registers, register prefetch staging.
#define KT       16
#define RT       128
#define ECH      4
#define NSTAGE   ((ECH*FDIM)/KT)   // 16
#define NTHREADS 512
#define LDSROW   132               // padded row: bank=(4k+srow)%32 -> 2-way max

// rbf(d,e) = exp(-((d-mu_e)/sigma)^2) = 2^(-(KC*(d-mu_e))^2)
#define KC_CONST   3.2029930899845557f
#define MU_STEP    (12.0f/31.0f)

__device__ __forceinline__ unsigned long long dup2(float x) {
    unsigned long long r;
    unsigned int u = __float_as_uint(x);
    asm("mov.b64 %0, {%1, %1};" : "=l"(r) : "r"(u));
    return r;
}
__device__ __forceinline__ void fma2(unsigned long long &acc,
                                     unsigned long long a,
                                     unsigned long long b) {
    asm("fma.rn.f32x2 %0, %1, %2, %0;" : "+l"(acc) : "l"(a), "l"(b));
}
__device__ __forceinline__ void unpack2(unsigned long long v, float &lo, float &hi) {
    unsigned int a, b;
    asm("mov.b64 {%0, %1}, %2;" : "=r"(a), "=r"(b) : "l"(v));
    lo = __uint_as_float(a);
    hi = __uint_as_float(b);
}
__device__ __forceinline__ float ex2a(float x) {
    float r; asm("ex2.approx.ftz.f32 %0, %1;" : "=f"(r) : "f"(x)); return r;
}
__device__ __forceinline__ float sqrta(float x) {
    float r; asm("sqrt.approx.f32 %0, %1;" : "=f"(r) : "f"(x)); return r;
}

__global__ void ff_init_kernel(float* out) {
    if (threadIdx.x < BATCH) out[threadIdx.x] = 0.0f;
}

__global__ void __launch_bounds__(NTHREADS, 1)
ff_main_kernel(const float* __restrict__ ligf,
               const float* __restrict__ recf,
               const float* __restrict__ ligc,
               const float* __restrict__ recc,
               float* __restrict__ out)
{
    // A tile [2][KT][LDSROW] + B tile [2][KT][LDSROW], fp32 (33792 B)
    __shared__ __align__(16) float smem[2 * KT * LDSROW * 2];
    float* As = smem;
    float* Bs = smem + 2 * KT * LDSROW;

    const int tid  = threadIdx.x;
    const int lane = tid & 31;         // owns r = 4*lane .. 4*lane+3
    const int w    = tid >> 5;         // warp id; owns l = w*8 .. w*8+7

    const int rt = blockIdx.x;         // 0..15
    const int ec = blockIdx.y;         // 0..7
    const int b  = blockIdx.z;         // 0..7

    const int r0    = rt * RT;
    const int e0    = ec * ECH;
    const int kbase = e0 * FDIM;

    const float* Ag = ligf + (size_t)b * LDIM * KTOT + kbase;
    const float* Bg = recf + (size_t)b * RDIM * KTOT + (size_t)r0 * KTOT + kbase;

    // staging: each thread loads one float4 (4 consecutive k) for one row
    const int srow = tid >> 2;          // 0..127
    const int scol = (tid & 3) * 4;     // 0,4,8,12

    // ---- stage-0 LDG first: latency covered by the sqrt burst below ----
    float4 pa, pb;
    pa = *(const float4*)(Ag + (size_t)srow * KTOT + scol);
    pb = *(const float4*)(Bg + (size_t)srow * KTOT + scol);

    // ---- distances for this thread's 8x4 pairs (registers) ----
    float dist[8][4];
    {
        float lx[8], ly[8], lz[8];
        #pragma unroll
        for (int i = 0; i < 8; i++) {
            const float* p = ligc + ((size_t)b * LDIM + w * 8 + i) * 3;
            lx[i] = p[0]; ly[i] = p[1]; lz[i] = p[2];
        }
        #pragma unroll
        for (int j = 0; j < 4; j++) {
            const float* p = recc + ((size_t)b * RDIM + r0 + 4 * lane + j) * 3;
            float rx = p[0], ry = p[1], rz = p[2];
            #pragma unroll
            for (int i = 0; i < 8; i++) {
                float dx = lx[i] - rx, dy = ly[i] - ry, dz = lz[i] - rz;
                float dd = fmaf(dx, dx, fmaf(dy, dy, dz * dz));
                dist[i][j] = sqrta(dd);
            }
        }
    }

    // acc[p][j] = packed {l = w*8+2p, w*8+2p+1} x r = 4*lane+j
    unsigned long long acc[4][4];
    #pragma unroll
    for (int p = 0; p < 4; p++)
        #pragma unroll
        for (int j = 0; j < 4; j++)
            acc[p][j] = 0ULL;

    float u_acc = 0.0f;

    #pragma unroll 1
    for (int s = 0; s < NSTAGE; s++) {
        const int buf = s & 1;
        float* Asb = As + buf * (KT * LDSROW);
        float* Bsb = Bs + buf * (KT * LDSROW);

        // store staged tile (padded row -> max 2-way bank conflict)
        {
            float va[4] = {pa.x, pa.y, pa.z, pa.w};
            float vb[4] = {pb.x, pb.y, pb.z, pb.w};
            #pragma unroll
            for (int j = 0; j < 4; j++) {
                Asb[(scol + j) * LDSROW + srow] = va[j];
                Bsb[(scol + j) * LDSROW + srow] = vb[j];
            }
        }
        __syncthreads();

        // prefetch next stage (lands during compute)
        if (s + 1 < NSTAGE) {
            pa = *(const float4*)(Ag + (size_t)srow * KTOT + (s + 1) * KT + scol);
            pb = *(const float4*)(Bg + (size_t)srow * KTOT + (s + 1) * KT + scol);
        }

        // ---- main compute: KT k-steps, 8L x 4R per thread via f32x2 ----
        #pragma unroll
        for (int k = 0; k < KT; k++) {
            // B first: feeds the longest chain (LDS -> dup2 -> FFMA2)
            float4 bf = *(const float4*)(Bsb + k * LDSROW + 4 * lane);
            // A: l-pairs, broadcast within warp (2x LDS.128)
            unsigned long long a2[4];
            {
                const ulonglong2* Ar =
                    (const ulonglong2*)(Asb + k * LDSROW + w * 8);
                ulonglong2 t0 = Ar[0];
                ulonglong2 t1 = Ar[1];
                a2[0] = t0.x; a2[1] = t0.y; a2[2] = t1.x; a2[3] = t1.y;
            }
            // interleave dup2 with the FMA stream: first FFMA2 issues as
            // soon as bf.x and a2 are ready, not after 4 movs
            {
                unsigned long long bx = dup2(bf.x);
                #pragma unroll
                for (int p = 0; p < 4; p++) fma2(acc[p][0], a2[p], bx);
            }
            {
                unsigned long long by = dup2(bf.y);
                #pragma unroll
                for (int p = 0; p < 4; p++) fma2(acc[p][1], a2[p], by);
            }
            {
                unsigned long long bz = dup2(bf.z);
                #pragma unroll
                for (int p = 0; p < 4; p++) fma2(acc[p][2], a2[p], bz);
            }
            {
                unsigned long long bw = dup2(bf.w);
                #pragma unroll
                for (int p = 0; p < 4; p++) fma2(acc[p][3], a2[p], bw);
            }
        }

        // ---- epilogue fold at each e boundary (every FDIM/KT = 4 stages) ----
        if ((s & 3) == 3) {
            const int e = e0 + (s >> 2);
            const float c2 = KC_CONST * MU_STEP * (float)e;
            #pragma unroll
            for (int p = 0; p < 4; p++) {
                #pragma unroll
                for (int j = 0; j < 4; j++) {
                    float dot0, dot1;
                    unpack2(acc[p][j], dot0, dot1);
                    float z0 = fmaf(dist[2 * p][j],     KC_CONST, -c2);
                    float z1 = fmaf(dist[2 * p + 1][j], KC_CONST, -c2);
                    u_acc = fmaf(ex2a(-z0 * z0), dot0, u_acc);
                    u_acc = fmaf(ex2a(-z1 * z1), dot1, u_acc);
                    acc[p][j] = 0ULL;
                }
            }
        }
    }

    // ---- block reduction + atomic accumulate into U[b] ----
    #pragma unroll
    for (int o = 16; o > 0; o >>= 1)
        u_acc += __shfl_xor_sync(0xffffffffu, u_acc, o);

    __syncthreads();                     // tiles done; reuse as scratch
    float* red = smem;
    if (lane == 0) red[w] = u_acc;
    __syncthreads();
    if (tid == 0) {
        float ssum = 0.0f;
        #pragma unroll
        for (int ww = 0; ww < NTHREADS / 32; ww++) ssum += red[ww];
        atomicAdd(out + b, ssum * 0.01f);   // ENERGY_SCALE
    }
}

extern "C" void kernel_launch(void* const* d_in, const int* in_sizes, int n_in,
                              void* d_out, int out_size) {
    (void)in_sizes; (void)n_in; (void)out_size;
    const float* lig_feat  = (const float*)d_in[0];
    const float* rec_feat  = (const float*)d_in[1];
    const float* lig_coord = (const float*)d_in[2];
    const float* rec_coord = (const float*)d_in[3];
    float* out = (float*)d_out;

    ff_init_kernel<<<1, 32>>>(out);

    dim3 grid(RDIM / RT, EDIM / ECH, BATCH);   // (16, 8, 8) = 1024 CTAs
    ff_main_kernel<<<grid, NTHREADS>>>(lig_feat, rec_feat,
                                       lig_coord, rec_coord, out);
}

// round 17
// speedup vs baseline: 1.8142x; 1.2766x over previous
#include <cuda_runtime.h>

// Problem constants
#define LDIM   128
#define RDIM   2048
#define EDIM   32
#define FDIM   64
#define KTOT   2048      // EDIM*FDIM, contiguous k per row
#define BATCH  8

// Tiling (R7 baseline): CTA = 128L x 128R x (ECH*64)k, 512 threads,
// thread tile 8L x 4R, dist in registers, register prefetch staging.
#define KT       16
#define RT       128
#define ECH      4
#define NTHREADS 512
#define LDSROW   132               // padded row: bank=(4k+srow)%32 -> 2-way max

// rbf(d,e) = exp(-((d-mu_e)/sigma)^2) = 2^(-(KC*(d-mu_e))^2)
#define KC_CONST   3.2029930899845557f
#define MU_STEP    (12.0f/31.0f)
// e contributes iff mu_e <= d + ECUT ; ECUT = 2.0 => |z| >= 5.33 sigma,
// rbf <= e^-28.4 ~ 5e-13 (truncation ~1e-10 relative, threshold is 1e-3)
#define ECUT       2.0f

__device__ __forceinline__ unsigned long long dup2(float x) {
    unsigned long long r;
    unsigned int u = __float_as_uint(x);
    asm("mov.b64 %0, {%1, %1};" : "=l"(r) : "r"(u));
    return r;
}
__device__ __forceinline__ void fma2(unsigned long long &acc,
                                     unsigned long long a,
                                     unsigned long long b) {
    asm("fma.rn.f32x2 %0, %1, %2, %0;" : "+l"(acc) : "l"(a), "l"(b));
}
__device__ __forceinline__ void unpack2(unsigned long long v, float &lo, float &hi) {
    unsigned int a, b;
    asm("mov.b64 {%0, %1}, %2;" : "=r"(a), "=r"(b) : "l"(v));
    lo = __uint_as_float(a);
    hi = __uint_as_float(b);
}
__device__ __forceinline__ float ex2a(float x) {
    float r; asm("ex2.approx.ftz.f32 %0, %1;" : "=f"(r) : "f"(x)); return r;
}
__device__ __forceinline__ float sqrta(float x) {
    float r; asm("sqrt.approx.f32 %0, %1;" : "=f"(r) : "f"(x)); return r;
}

__global__ void ff_init_kernel(float* out) {
    if (threadIdx.x < BATCH) out[threadIdx.x] = 0.0f;
}

__global__ void __launch_bounds__(NTHREADS, 1)
ff_main_kernel(const float* __restrict__ ligf,
               const float* __restrict__ recf,
               const float* __restrict__ ligc,
               const float* __restrict__ recc,
               float* __restrict__ out)
{
    // A tile [2][KT][LDSROW] + B tile [2][KT][LDSROW], fp32 (33792 B)
    __shared__ __align__(16) float smem[2 * KT * LDSROW * 2];
    float* As = smem;
    float* Bs = smem + 2 * KT * LDSROW;

    const int tid  = threadIdx.x;
    const int lane = tid & 31;         // owns r = 4*lane .. 4*lane+3
    const int w    = tid >> 5;         // warp id; owns l = w*8 .. w*8+7

    const int rt = blockIdx.x;         // 0..15
    const int ec = blockIdx.y;         // 0..7
    const int b  = blockIdx.z;         // 0..7

    const int r0    = rt * RT;
    const int e0    = ec * ECH;
    const int kbase = e0 * FDIM;

    const float* Ag = ligf + (size_t)b * LDIM * KTOT + kbase;
    const float* Bg = recf + (size_t)b * RDIM * KTOT + (size_t)r0 * KTOT + kbase;

    // staging: each thread loads one float4 (4 consecutive k) for one row
    const int srow = tid >> 2;          // 0..127
    const int scol = (tid & 3) * 4;     // 0,4,8,12

    // ---- stage-0 LDG first: latency covered by the sqrt burst below ----
    float4 pa, pb;
    pa = *(const float4*)(Ag + (size_t)srow * KTOT + scol);
    pb = *(const float4*)(Bg + (size_t)srow * KTOT + scol);

    // ---- distances for this thread's 8x4 pairs (registers) ----
    float dist[8][4];
    {
        float lx[8], ly[8], lz[8];
        #pragma unroll
        for (int i = 0; i < 8; i++) {
            const float* p = ligc + ((size_t)b * LDIM + w * 8 + i) * 3;
            lx[i] = p[0]; ly[i] = p[1]; lz[i] = p[2];
        }
        #pragma unroll
        for (int j = 0; j < 4; j++) {
            const float* p = recc + ((size_t)b * RDIM + r0 + 4 * lane + j) * 3;
            float rx = p[0], ry = p[1], rz = p[2];
            #pragma unroll
            for (int i = 0; i < 8; i++) {
                float dx = lx[i] - rx, dy = ly[i] - ry, dz = lz[i] - rz;
                float dd = fmaf(dx, dx, fmaf(dy, dy, dz * dz));
                dist[i][j] = sqrta(dd);
            }
        }
    }

    // ---- CTA-wide d_max -> adaptive e range for this chunk ----
    int NS;                             // number of stages to run (4 per e)
    {
        float dm = 0.0f;
        #pragma unroll
        for (int p = 0; p < 8; p++)
            #pragma unroll
            for (int j = 0; j < 4; j++)
                dm = fmaxf(dm, dist[p][j]);
        #pragma unroll
        for (int o = 16; o > 0; o >>= 1)
            dm = fmaxf(dm, __shfl_xor_sync(0xffffffffu, dm, o));
        float* red = smem;              // scratch before stage-0 STS
        if (lane == 0) red[w] = dm;
        __syncthreads();
        float d_max = red[0];
        #pragma unroll
        for (int ww = 1; ww < NTHREADS / 32; ww++)
            d_max = fmaxf(d_max, red[ww]);
        __syncthreads();                // scratch consumed; safe to overwrite

        // e contributes iff e*MU_STEP <= d_max + ECUT
        const float elim = (d_max + ECUT) / MU_STEP;
        int n_e = 0;
        #pragma unroll
        for (int i = 0; i < ECH; i++)
            if ((float)(e0 + i) <= elim) n_e = i + 1;
        NS = 4 * n_e;
    }
    if (NS == 0) return;                // whole chunk negligible: CTA exits

    // acc[p][j] = packed {l = w*8+2p, w*8+2p+1} x r = 4*lane+j
    unsigned long long acc[4][4];
    #pragma unroll
    for (int p = 0; p < 4; p++)
        #pragma unroll
        for (int j = 0; j < 4; j++)
            acc[p][j] = 0ULL;

    float u_acc = 0.0f;

    #pragma unroll 1
    for (int s = 0; s < NS; s++) {
        const int buf = s & 1;
        float* Asb = As + buf * (KT * LDSROW);
        float* Bsb = Bs + buf * (KT * LDSROW);

        // store staged tile (padded row -> max 2-way bank conflict)
        {
            float va[4] = {pa.x, pa.y, pa.z, pa.w};
            float vb[4] = {pb.x, pb.y, pb.z, pb.w};
            #pragma unroll
            for (int j = 0; j < 4; j++) {
                Asb[(scol + j) * LDSROW + srow] = va[j];
                Bsb[(scol + j) * LDSROW + srow] = vb[j];
            }
        }
        __syncthreads();

        // prefetch next stage (lands during compute)
        if (s + 1 < NS) {
            pa = *(const float4*)(Ag + (size_t)srow * KTOT + (s + 1) * KT + scol);
            pb = *(const float4*)(Bg + (size_t)srow * KTOT + (s + 1) * KT + scol);
        }

        // ---- main compute: KT k-steps, 8L x 4R per thread via f32x2 ----
        #pragma unroll
        for (int k = 0; k < KT; k++) {
            // B first: feeds the longest chain (LDS -> dup2 -> FFMA2)
            float4 bf = *(const float4*)(Bsb + k * LDSROW + 4 * lane);
            // A: l-pairs, broadcast within warp (2x LDS.128)
            unsigned long long a2[4];
            {
                const ulonglong2* Ar =
                    (const ulonglong2*)(Asb + k * LDSROW + w * 8);
                ulonglong2 t0 = Ar[0];
                ulonglong2 t1 = Ar[1];
                a2[0] = t0.x; a2[1] = t0.y; a2[2] = t1.x; a2[3] = t1.y;
            }
            {
                unsigned long long bx = dup2(bf.x);
                #pragma unroll
                for (int p = 0; p < 4; p++) fma2(acc[p][0], a2[p], bx);
            }
            {
                unsigned long long by = dup2(bf.y);
                #pragma unroll
                for (int p = 0; p < 4; p++) fma2(acc[p][1], a2[p], by);
            }
            {
                unsigned long long bz = dup2(bf.z);
                #pragma unroll
                for (int p = 0; p < 4; p++) fma2(acc[p][2], a2[p], bz);
            }
            {
                unsigned long long bw = dup2(bf.w);
                #pragma unroll
                for (int p = 0; p < 4; p++) fma2(acc[p][3], a2[p], bw);
            }
        }

        // ---- epilogue fold at each e boundary (every FDIM/KT = 4 stages) ----
        if ((s & 3) == 3) {
            const int e = e0 + (s >> 2);
            const float c2 = KC_CONST * MU_STEP * (float)e;
            #pragma unroll
            for (int p = 0; p < 4; p++) {
                #pragma unroll
                for (int j = 0; j < 4; j++) {
                    float dot0, dot1;
                    unpack2(acc[p][j], dot0, dot1);
                    float z0 = fmaf(dist[2 * p][j],     KC_CONST, -c2);
                    float z1 = fmaf(dist[2 * p + 1][j], KC_CONST, -c2);
                    u_acc = fmaf(ex2a(-z0 * z0), dot0, u_acc);
                    u_acc = fmaf(ex2a(-z1 * z1), dot1, u_acc);
                    acc[p][j] = 0ULL;
                }
            }
        }
    }

    // ---- block reduction + atomic accumulate into U[b] ----
    #pragma unroll
    for (int o = 16; o > 0; o >>= 1)
        u_acc += __shfl_xor_sync(0xffffffffu, u_acc, o);

    __syncthreads();                     // tiles done; reuse as scratch
    float* red = smem;
    if (lane == 0) red[w] = u_acc;
    __syncthreads();
    if (tid == 0) {
        float ssum = 0.0f;
        #pragma unroll
        for (int ww = 0; ww < NTHREADS / 32; ww++) ssum += red[ww];
        atomicAdd(out + b, ssum * 0.01f);   // ENERGY_SCALE
    }
}

extern "C" void kernel_launch(void* const* d_in, const int* in_sizes, int n_in,
                              void* d_out, int out_size) {
    (void)in_sizes; (void)n_in; (void)out_size;
    const float* lig_feat  = (const float*)d_in[0];
    const float* rec_feat  = (const float*)d_in[1];
    const float* lig_coord = (const float*)d_in[2];
    const float* rec_coord = (const float*)d_in[3];
    float* out = (float*)d_out;

    ff_init_kernel<<<1, 32>>>(out);

    dim3 grid(RDIM / RT, EDIM / ECH, BATCH);   // (16, 8, 8) = 1024 CTAs
    ff_main_kernel<<<grid, NTHREADS>>>(lig_feat, rec_feat,
                                       lig_coord, rec_coord, out);
}